// round 8
// baseline (speedup 1.0000x reference)
#include <cuda_runtime.h>

#define B_TOT    8192
#define T_LEN    512
#define F_IN     24
#define H_DIM    12
#define CHUNK    8
#define EPB      16           // batch elements per block
#define NTHREADS (EPB * 4)    // 64 (4 threads per element, 3 h-rows each)
#define NCHUNK   (T_LEN / CHUNK)
#define NBUF     3            // triple buffer: consume c, project c+1, load c+2
#define XS_STRIDE 28          // padded floats per (tt, elem) row
#define XS_BUF_FLOATS (CHUNK * EPB * XS_STRIDE)
#define SMEM_BYTES (NBUF * XS_BUF_FLOATS * 4)

typedef unsigned long long u64;

__device__ __forceinline__ unsigned smem_u32(const void* p) {
    return (unsigned)__cvta_generic_to_shared(p);
}
__device__ __forceinline__ void cp_async16(unsigned dst, const void* src) {
    asm volatile("cp.async.cg.shared.global [%0], [%1], 16;\n" :: "r"(dst), "l"(src));
}
__device__ __forceinline__ void cp_commit() {
    asm volatile("cp.async.commit_group;\n" ::: "memory");
}
template <int N> __device__ __forceinline__ void cp_wait() {
    asm volatile("cp.async.wait_group %0;\n" :: "n"(N) : "memory");
}

// ---- packed f32x2 helpers ----
__device__ __forceinline__ u64 pack2(float lo, float hi) {
    u64 d; asm("mov.b64 %0, {%1, %2};" : "=l"(d) : "f"(lo), "f"(hi)); return d;
}
__device__ __forceinline__ void unpack2(u64 d, float& lo, float& hi) {
    asm("mov.b64 {%0, %1}, %2;" : "=f"(lo), "=f"(hi) : "l"(d));
}
__device__ __forceinline__ u64 fma2(u64 a, u64 b, u64 c) {
    u64 d; asm("fma.rn.f32x2 %0, %1, %2, %3;" : "=l"(d) : "l"(a), "l"(b), "l"(c)); return d;
}
__device__ __forceinline__ u64 add2(u64 a, u64 b) {
    u64 d; asm("add.rn.f32x2 %0, %1, %2;" : "=l"(d) : "l"(a), "l"(b)); return d;
}
__device__ __forceinline__ float hadd2(u64 a) {
    float lo, hi; unpack2(a, lo, hi); return lo + hi;
}

// tanh(x) = 1 - 2*rcp(exp(2x)+1); 5 instrs, correct saturation at +/-inf.
__device__ __forceinline__ float tanh_fast(float x) {
    float e;
    asm("ex2.approx.f32 %0, %1;" : "=f"(e) : "f"(x * 2.885390082f));
    float r;
    asm("rcp.approx.f32 %0, %1;" : "=f"(r) : "f"(e + 1.0f));
    return fmaf(-2.0f, r, 1.0f);
}

__global__ void __launch_bounds__(NTHREADS) rnn_fused_kernel(
    const float* __restrict__ x,
    const float* __restrict__ W_ih, const float* __restrict__ b_ih,
    const float* __restrict__ W_hh, const float* __restrict__ b_hh,
    const float* __restrict__ W1,   const float* __restrict__ b1,
    const float* __restrict__ W2,   const float* __restrict__ b2,
    const float* __restrict__ W3,   const float* __restrict__ b3,
    float* __restrict__ out)
{
    extern __shared__ float xs[];  // [NBUF][CHUNK][EPB][XS_STRIDE]
    __shared__ float sW1[144], sW2[144], sb1[12], sb2[12], sW3[12], sb3[1];

    const int tid  = threadIdx.x;
    const int e    = tid >> 2;        // element within block
    const int sub  = tid & 3;         // which 3 h-rows this thread owns
    const int lane = tid & 31;
    const int b    = blockIdx.x * EPB + e;
    const int j0   = sub * 3;

    for (int i = tid; i < 144; i += NTHREADS) { sW1[i] = W1[i]; sW2[i] = W2[i]; }
    if (tid < 12) { sb1[tid] = b1[tid]; sb2[tid] = b2[tid]; sW3[tid] = W3[tid]; }
    if (tid == 0) sb3[0] = b3[0];

    // Per-thread weights, packed along contraction dim. Bias kept scalar.
    u64 wih2[3][F_IN / 2], whh2[3][H_DIM / 2];
    float biasS[3];
    #pragma unroll
    for (int c = 0; c < 3; c++) {
        const int j = j0 + c;
        #pragma unroll
        for (int p = 0; p < F_IN / 2; p++)
            wih2[c][p] = pack2(W_ih[j * F_IN + 2 * p], W_ih[j * F_IN + 2 * p + 1]);
        #pragma unroll
        for (int p = 0; p < H_DIM / 2; p++)
            whh2[c][p] = pack2(W_hh[j * H_DIM + 2 * p], W_hh[j * H_DIM + 2 * p + 1]);
        biasS[c] = b_ih[j] + b_hh[j];
    }

    // cp.async staging: thread (e,sub) loads timesteps {2*sub, 2*sub+1} of elem e.
    const float* src0 = x + ((long)b * T_LEN + 2 * sub) * F_IN;
    const unsigned dst0 = smem_u32(xs) + (unsigned)(((2 * sub * EPB + e) * XS_STRIDE) * 4);

    auto load_chunk = [&](int bufidx, int c) {
        const float* s = src0 + (long)c * (CHUNK * F_IN);
        const unsigned d = dst0 + (unsigned)(bufidx * (XS_BUF_FLOATS * 4));
        #pragma unroll
        for (int j = 0; j < 12; j++) {
            const int tt_l = j / 6;
            const int q    = j % 6;
            cp_async16(d + (unsigned)((tt_l * EPB * XS_STRIDE + q * 4) * 4),
                       s + tt_l * F_IN + q * 4);
        }
        cp_commit();
    };

    // Input projection for one timestep row (12 FFMA2 + 3 hadd per 3 rows)
    auto projA = [&](const float* xrow, float xp[3]) {
        const ulonglong2* xr = (const ulonglong2*)xrow;
        u64 a0 = 0ull, a1 = 0ull, a2 = 0ull;
        #pragma unroll
        for (int q = 0; q < 6; q++) {
            ulonglong2 v = xr[q];
            a0 = fma2(wih2[0][2 * q + 0], v.x, a0);
            a1 = fma2(wih2[1][2 * q + 0], v.x, a1);
            a2 = fma2(wih2[2][2 * q + 0], v.x, a2);
            a0 = fma2(wih2[0][2 * q + 1], v.y, a0);
            a1 = fma2(wih2[1][2 * q + 1], v.y, a1);
            a2 = fma2(wih2[2][2 * q + 1], v.y, a2);
        }
        xp[0] = hadd2(a0) + biasS[0];
        xp[1] = hadd2(a1) + biasS[1];
        xp[2] = hadd2(a2) + biasS[2];
    };

    u64 hp[H_DIM / 2];
    #pragma unroll
    for (int k = 0; k < H_DIM / 2; k++) hp[k] = 0ull;

    const u64 ZERO2 = 0ull;
    const int qbase = lane & ~3;

    // One serial recurrence step given precomputed xp; updates hp.
    auto stepB = [&](const float xp[3]) {
        float hl[3];
        #pragma unroll
        for (int cc = 0; cc < 3; cc++) {
            u64 sA = fma2(whh2[cc][0], hp[0], pack2(xp[cc], 0.0f));
            sA = fma2(whh2[cc][1], hp[1], sA);
            sA = fma2(whh2[cc][2], hp[2], sA);
            u64 sB = fma2(whh2[cc][3], hp[3], ZERO2);
            sB = fma2(whh2[cc][4], hp[4], sB);
            sB = fma2(whh2[cc][5], hp[5], sB);
            hl[cc] = tanh_fast(hadd2(add2(sA, sB)));
        }
        float hs[H_DIM];
        #pragma unroll
        for (int s = 0; s < 4; s++) {
            #pragma unroll
            for (int cc = 0; cc < 3; cc++)
                hs[s * 3 + cc] = __shfl_sync(0xffffffffu, hl[cc], qbase + s);
        }
        #pragma unroll
        for (int p = 0; p < H_DIM / 2; p++)
            hp[p] = pack2(hs[2 * p], hs[2 * p + 1]);
    };

    // ---- pipeline prologue: chunks 0 and 1 in flight ----
    load_chunk(0, 0);
    load_chunk(1, 1);
    cp_wait<1>();        // chunk 0 arrived
    __syncthreads();

    float xpc[CHUNK][3], xpn[CHUNK][3];
    {
        const float* buf0 = xs;
        #pragma unroll
        for (int tt = 0; tt < CHUNK; tt++)
            projA(buf0 + (tt * EPB + e) * XS_STRIDE, xpc[tt]);
    }

    // ---- main loop: B(c) interleaved with A(c+1); prefetch c+2 ----
    for (int c = 0; c < NCHUNK - 1; c++) {
        if (c + 2 < NCHUNK) { load_chunk((c + 2) % NBUF, c + 2); cp_wait<1>(); }
        else                { cp_wait<0>(); }
        __syncthreads();   // chunk c+1 visible; buf[(c+2)%NBUF] safe to overwrite

        const float* bufn = xs + ((c + 1) % NBUF) * XS_BUF_FLOATS;

        #pragma unroll
        for (int tt = 0; tt < CHUNK; tt++) {
            // serial recurrence for step tt of chunk c (chain-bound)...
            stepB(xpc[tt]);
            // ...interleaved with chain-independent projection of chunk c+1
            projA(bufn + (tt * EPB + e) * XS_STRIDE, xpn[tt]);
        }
        #pragma unroll
        for (int tt = 0; tt < CHUNK; tt++) {
            xpc[tt][0] = xpn[tt][0];
            xpc[tt][1] = xpn[tt][1];
            xpc[tt][2] = xpn[tt][2];
        }
    }

    // ---- epilogue: last chunk, recurrence only ----
    #pragma unroll
    for (int tt = 0; tt < CHUNK; tt++)
        stepB(xpc[tt]);

    // MLP head: one thread per element
    if (sub == 0) {
        float h_all[H_DIM];
        #pragma unroll
        for (int p = 0; p < H_DIM / 2; p++) unpack2(hp[p], h_all[2 * p], h_all[2 * p + 1]);
        float o1[H_DIM], o2[H_DIM];
        #pragma unroll
        for (int j = 0; j < H_DIM; j++) {
            float s = sb1[j];
            #pragma unroll
            for (int k = 0; k < H_DIM; k++) s = fmaf(sW1[j * H_DIM + k], h_all[k], s);
            o1[j] = fmaxf(s, 0.0f);
        }
        #pragma unroll
        for (int j = 0; j < H_DIM; j++) {
            float s = sb2[j];
            #pragma unroll
            for (int k = 0; k < H_DIM; k++) s = fmaf(sW2[j * H_DIM + k], o1[k], s);
            o2[j] = fmaxf(s, 0.0f);
        }
        float s = sb3[0];
        #pragma unroll
        for (int k = 0; k < H_DIM; k++) s = fmaf(sW3[k], o2[k], s);
        out[b] = s;
    }
}

extern "C" void kernel_launch(void* const* d_in, const int* in_sizes, int n_in,
                              void* d_out, int out_size) {
    (void)in_sizes; (void)n_in; (void)out_size;
    const float* x    = (const float*)d_in[0];
    const float* W_ih = (const float*)d_in[1];
    const float* b_ih = (const float*)d_in[2];
    const float* W_hh = (const float*)d_in[3];
    const float* b_hh = (const float*)d_in[4];
    const float* W1   = (const float*)d_in[5];
    const float* b1   = (const float*)d_in[6];
    const float* W2   = (const float*)d_in[7];
    const float* b2   = (const float*)d_in[8];
    const float* W3   = (const float*)d_in[9];
    const float* b3   = (const float*)d_in[10];
    float* out = (float*)d_out;

    cudaFuncSetAttribute(rnn_fused_kernel,
                         cudaFuncAttributeMaxDynamicSharedMemorySize, SMEM_BYTES);

    dim3 grid(B_TOT / EPB);   // 512 blocks
    dim3 block(NTHREADS);     // 64 threads
    rnn_fused_kernel<<<grid, block, SMEM_BYTES>>>(
        x, W_ih, b_ih, W_hh, b_hh, W1, b1, W2, b2, W3, b3, out);
}